// round 1
// baseline (speedup 1.0000x reference)
#include <cuda_runtime.h>
#include <cuda_bf16.h>

// Problem shape (fixed by the dataset): s1, blur: [4, 10, 256, 256] fp32.
// Output: [4, 256, 256] fp32.
//
// Per pixel p:
//   lo_j = s1_j - blur_j, hi_j = s1_j + blur_j
//   candidate i (i = 0..n): x_j = hi_j for j < i else lo_j
//   pick i minimizing std(x) (ddof=1)  ==  minimizing M_i = n*Σx² - (Σx)²
//   output mean(x) = Σx / n  of the winning candidate.
//
// Incremental across i: flipping plane i from lo to hi does
//   sum += 2*blur_i ;  sumsq += (s+b)² - (s-b)² = 4*s_i*blur_i
// Comparator kept in FP64 so the argmin equals the exact argmin of the
// fp32 inputs (avoids fp32 catastrophic-cancellation tie flips vs reference).

#define NPLANES 10
#define HW      65536  // 256*256

__global__ __launch_bounds__(256)
void distregression_kernel(const float* __restrict__ s1,
                           const float* __restrict__ blur,
                           float* __restrict__ out,
                           int npix)
{
    int pix = blockIdx.x * blockDim.x + threadIdx.x;
    if (pix >= npix) return;

    int b  = pix >> 16;          // pix / HW
    int hw = pix & (HW - 1);     // pix % HW

    const float* s1p = s1   + (size_t)b * NPLANES * HW + hw;
    const float* blp = blur + (size_t)b * NPLANES * HW + hw;

    // Front-batch all 20 coalesced loads (max MLP).
    float sv[NPLANES], bv[NPLANES];
    #pragma unroll
    for (int j = 0; j < NPLANES; j++) {
        sv[j] = __ldg(s1p + j * HW);
        bv[j] = __ldg(blp + j * HW);
    }

    // Candidate i = 0: all lo.
    double sum = 0.0, sq = 0.0;
    #pragma unroll
    for (int j = 0; j < NPLANES; j++) {
        double lo = (double)sv[j] - (double)bv[j];   // exact in double
        sum += lo;
        sq   = fma(lo, lo, sq);
    }

    double bestM   = 1.0e300;
    double bestSum = 0.0;

    #pragma unroll
    for (int i = 0; i <= NPLANES; i++) {
        // M = n*sq - sum^2 ; argmin M == argmin variance == argmin std.
        double M = fma(-sum, sum, (double)NPLANES * sq);
        if (M < bestM) {            // strict < keeps first index on ties,
            bestM   = M;            // matching jnp.argmin tie-break.
            bestSum = sum;
        }
        if (i < NPLANES) {
            double bj = (double)bv[i];
            double sj = (double)sv[i];
            sum += 2.0 * bj;
            sq   = fma(4.0 * sj, bj, sq);   // hi^2 - lo^2 = 4*s*b exactly
        }
    }

    out[pix] = (float)(bestSum * (1.0 / (double)NPLANES));
}

extern "C" void kernel_launch(void* const* d_in, const int* in_sizes, int n_in,
                              void* d_out, int out_size)
{
    const float* s1   = (const float*)d_in[0];
    const float* blur = (const float*)d_in[1];
    float* out = (float*)d_out;

    int npix = out_size;               // bs*H*W = 262144
    int threads = 256;
    int blocks  = (npix + threads - 1) / threads;
    distregression_kernel<<<blocks, threads>>>(s1, blur, out, npix);
}

// round 2
// speedup vs baseline: 10.0097x; 10.0097x over previous
#include <cuda_runtime.h>
#include <cuda_bf16.h>

// s1, blur: [4, 10, 256, 256] fp32 -> out: [4, 256, 256] fp32.
//
// Per pixel: candidate i (0..10): x_j = s_j + b_j for j<i else s_j - b_j.
// Pick i minimizing variance (== std, == M_i = sumsq - sum^2/n), output sum/n.
// Incremental across i: sum += 2*b_i ; sumsq += (s+b)^2-(s-b)^2 = 4*s_i*b_i.
// All FP32 (FP64 pipe on B300 was the 66us bottleneck in round 0; near-tie
// argmin flips only happen when b_i ~ 0, where the output is insensitive).
//
// 4 pixels per thread via float4 loads (LDG.128, 20 loads/thread).

#define NPLANES 10
#define HW      65536   // 256*256
#define HW4     16384   // HW / 4

__global__ __launch_bounds__(256)
void distregression_kernel(const float4* __restrict__ s1,
                           const float4* __restrict__ blur,
                           float4* __restrict__ out,
                           int nquads)
{
    int t = blockIdx.x * blockDim.x + threadIdx.x;
    if (t >= nquads) return;

    int b   = t >> 14;            // quad index / HW4  -> batch
    int hw4 = t & (HW4 - 1);      // quad index within image

    const float4* s1p = s1   + (size_t)b * NPLANES * HW4 + hw4;
    const float4* blp = blur + (size_t)b * NPLANES * HW4 + hw4;

    // Front-batch all 20 vector loads (max MLP).
    float sv[NPLANES][4], bv[NPLANES][4];
    #pragma unroll
    for (int j = 0; j < NPLANES; j++) {
        float4 s = __ldg(s1p + j * HW4);
        float4 v = __ldg(blp + j * HW4);
        sv[j][0] = s.x; sv[j][1] = s.y; sv[j][2] = s.z; sv[j][3] = s.w;
        bv[j][0] = v.x; bv[j][1] = v.y; bv[j][2] = v.z; bv[j][3] = v.w;
    }

    float res[4];
    #pragma unroll
    for (int k = 0; k < 4; k++) {
        // Candidate i = 0: all lo = s - b.
        float sum = 0.f, sq = 0.f;
        #pragma unroll
        for (int j = 0; j < NPLANES; j++) {
            float lo = sv[j][k] - bv[j][k];
            sum += lo;
            sq   = fmaf(lo, lo, sq);
        }

        float bestM   = 3.0e38f;
        float bestSum = sum;

        #pragma unroll
        for (int i = 0; i <= NPLANES; i++) {
            float m = sum * (1.0f / NPLANES);
            float M = fmaf(-sum, m, sq);      // sumsq - sum^2/n (~variance*n)
            if (M < bestM) {                   // strict <: first index wins ties
                bestM   = M;
                bestSum = sum;
            }
            if (i < NPLANES) {
                sum = fmaf(2.0f, bv[i][k], sum);
                sq  = fmaf(4.0f * sv[i][k], bv[i][k], sq);
            }
        }
        res[k] = bestSum * (1.0f / NPLANES);
    }

    out[t] = make_float4(res[0], res[1], res[2], res[3]);
}

extern "C" void kernel_launch(void* const* d_in, const int* in_sizes, int n_in,
                              void* d_out, int out_size)
{
    const float4* s1   = (const float4*)d_in[0];
    const float4* blur = (const float4*)d_in[1];
    float4* out = (float4*)d_out;

    int nquads  = out_size / 4;          // 65536
    int threads = 256;
    int blocks  = (nquads + threads - 1) / threads;   // 256
    distregression_kernel<<<blocks, threads>>>(s1, blur, out, nquads);
}